// round 1
// baseline (speedup 1.0000x reference)
#include <cuda_runtime.h>
#include <math.h>

// YOLOv1 loss, B x 7 x 7 x 30 fp32 inputs.
// Key algebraic simplification: max_iou is only tested against 0, and union>0
// always, so cmask reduces to "exists a masked pred box with intersection>0".
// Intersection arithmetic replicates the reference bit-for-bit
// (cx - w/2 etc., exact min/max/sub), so the >0 decision is exact.

#define CELLS 49
#define CH 30
#define FPS (CELLS * CH)  // 1470 floats per sample per tensor
#define NSLOT 128         // atomic slot spreading to avoid L2 same-address serialization

// accumulator layout: [0]=noobj, [1]=cls, [2]=coord, [3]=objconf ; NSLOT slots each
__device__ double g_acc[4 * NSLOT];

__global__ void zero_acc_kernel() {
    int i = blockIdx.x * blockDim.x + threadIdx.x;
    if (i < 4 * NSLOT) g_acc[i] = 0.0;
}

__global__ __launch_bounds__(128) void yolo_main_kernel(
    const float* __restrict__ pred, const float* __restrict__ target)
{
    __shared__ float sp[FPS];
    __shared__ float st[FPS];
    __shared__ int s_cells[CELLS];
    __shared__ int s_ncells;
    __shared__ float s_part[4][4];

    const int tid = threadIdx.x;
    const int b = blockIdx.x;

    // coalesced float2 staging of both tensors (1470 floats = 735 float2 each;
    // sample stride 5880 B is 8B-aligned so float2 is safe)
    const float2* gp = (const float2*)(pred + (size_t)b * FPS);
    const float2* gt = (const float2*)(target + (size_t)b * FPS);
    float2* sp2 = (float2*)sp;
    float2* st2 = (float2*)st;
    if (tid == 0) s_ncells = 0;
    #pragma unroll 3
    for (int i = tid; i < FPS / 2; i += 128) {
        sp2[i] = gp[i];
        st2[i] = gt[i];
    }
    __syncthreads();

    float noobj = 0.f, cls = 0.f, coord = 0.f, objc = 0.f;

    // ---- phase 1: per-cell noobj / class terms + obj-cell compaction ----
    if (tid < CELLS) {
        const float* tc = st + tid * CH;
        const float* pc = sp + tid * CH;
        float conf = tc[4];  // exactly 0.0 or 1.0
        if (conf == 0.f) {
            float d4 = pc[4] - tc[4];
            float d9 = pc[9] - tc[9];
            noobj = d4 * d4 + d9 * d9;
        } else {
            float s = 0.f;
            #pragma unroll
            for (int k = 10; k < CH; k++) {
                float d = pc[k] - tc[k];
                s += d * d;
            }
            cls = s;
            s_cells[atomicAdd(&s_ncells, 1)] = tid;
        }
    }
    __syncthreads();

    // ---- phase 2: per obj box — overlap existence + coord/conf losses ----
    const int nbox = 2 * s_ncells;
    if (tid < nbox) {
        const int cell = s_cells[tid >> 1];
        const int off = cell * CH + 5 * (tid & 1);
        const float* tb = st + off;
        const float tcx = tb[0], tcy = tb[1], tw = tb[2], th = tb[3];
        // replicate reference: cx - w/2 etc. (exact halving)
        const float tx0 = tcx - 0.5f * tw, ty0 = tcy - 0.5f * th;
        const float tx1 = tcx + 0.5f * tw, ty1 = tcy + 0.5f * th;

        bool found = false;
        for (int j = 0; j < nbox; j++) {
            const int po = s_cells[j >> 1] * CH + 5 * (j & 1);
            const float pcx = sp[po], pcy = sp[po + 1];
            const float pw = sp[po + 2], ph = sp[po + 3];
            // wh = clip(rb - lt, 0); inter = wh.x * wh.y ; inter>0 <=> iou>0
            const float ix = fminf(pcx + 0.5f * pw, tx1) - fmaxf(pcx - 0.5f * pw, tx0);
            const float iy = fminf(pcy + 0.5f * ph, ty1) - fmaxf(pcy - 0.5f * ph, ty0);
            if (ix > 0.f && iy > 0.f && ix * iy > 0.f) { found = true; break; }
        }

        if (found) {
            const float* pb = sp + off;
            const float dx = pb[0] - tb[0];
            const float dy = pb[1] - tb[1];
            const float dw = sqrtf(pb[2]) - sqrtf(tb[2]);
            const float dh = sqrtf(pb[3]) - sqrtf(tb[3]);
            coord = dx * dx + dy * dy + dw * dw + dh * dh;
            const float dc = pb[4] - tb[4];
            objc = dc * dc;
        }
    }

    // ---- block reduction: 4 scalars over 128 threads ----
    float v0 = noobj, v1 = cls, v2 = coord, v3 = objc;
    #pragma unroll
    for (int o = 16; o > 0; o >>= 1) {
        v0 += __shfl_down_sync(0xffffffffu, v0, o);
        v1 += __shfl_down_sync(0xffffffffu, v1, o);
        v2 += __shfl_down_sync(0xffffffffu, v2, o);
        v3 += __shfl_down_sync(0xffffffffu, v3, o);
    }
    const int warp = tid >> 5, lane = tid & 31;
    if (lane == 0) {
        s_part[0][warp] = v0;
        s_part[1][warp] = v1;
        s_part[2][warp] = v2;
        s_part[3][warp] = v3;
    }
    __syncthreads();
    if (tid < 4) {
        float s = s_part[tid][0] + s_part[tid][1] + s_part[tid][2] + s_part[tid][3];
        atomicAdd(&g_acc[tid * NSLOT + (b & (NSLOT - 1))], (double)s);
    }
}

__global__ void final_kernel(float* __restrict__ out, int B) {
    __shared__ double r[4];
    const int t = threadIdx.x;  // blockDim = 4
    double s = 0.0;
    for (int i = 0; i < NSLOT; i++) s += g_acc[t * NSLOT + i];
    r[t] = s;
    __syncthreads();
    if (t == 0) {
        const double inv = 1.0 / (double)B;
        const double cls = r[1] * inv;
        const double obj = (r[3] + 0.5 * r[0]) * inv;
        const double coord = r[2] * 5.0 * inv;
        out[0] = (float)(cls + obj + coord);
        out[1] = (float)cls;
        out[2] = (float)obj;
        out[3] = (float)coord;
    }
}

extern "C" void kernel_launch(void* const* d_in, const int* in_sizes, int n_in,
                              void* d_out, int out_size)
{
    const float* pred = (const float*)d_in[0];
    const float* target = (const float*)d_in[1];
    const int B = in_sizes[0] / FPS;

    zero_acc_kernel<<<(4 * NSLOT + 127) / 128, 128>>>();
    yolo_main_kernel<<<B, 128>>>(pred, target);
    final_kernel<<<1, 4>>>((float*)d_out, B);
}